// round 6
// baseline (speedup 1.0000x reference)
#include <cuda_runtime.h>
#include <cuda_bf16.h>

#define FEAT      4096
#define NTHREADS  512
#define PER       8           // FEAT / NTHREADS
#define SEL_RANK  2048u       // 0-indexed rank of smallest KEPT element
#define SCALE     2.0f        // FEAT / NACTIVE
#define NBINS     2048
#define CAND_MAX  512
#define K_LO      0x41FFFFFFu   // fkey(-0.125f)
#define K_HI      0xBE000000u   // fkey(+0.125f)
#define BIN_BASE  0x41Fu        // K_LO >> 20

// monotone fp32 -> u32 key (ascending float order == ascending uint order)
__device__ __forceinline__ unsigned int fkey(float f) {
    unsigned int u = __float_as_uint(f);
    return u ^ ((unsigned int)((int)u >> 31) | 0x80000000u);
}
// inverse key -> fp32 (branchless)
__device__ __forceinline__ float kinv(unsigned int k) {
    unsigned int m = (unsigned int)((int)(~k) >> 31) | 0x80000000u;
    return __uint_as_float(k ^ m);
}

// Scan a 2048-bin shared histogram (4 bins/thread), select the bin containing
// `rank`. Writes s_pr[0]=bin, s_pr[1]=rank-within-bin. If rank is out of range
// (including unsigned wrap), nothing is written. Contains 2 __syncthreads().
__device__ __forceinline__ void scan_select(unsigned int* hist, unsigned int* wsum,
                                            unsigned int* s_pr, unsigned int rank,
                                            int tid, unsigned int lane, unsigned int wid)
{
    uint4 a = reinterpret_cast<uint4*>(hist)[tid];
    const unsigned int csum = a.x + a.y + a.z + a.w;
    unsigned int v = csum;
    #pragma unroll
    for (int off = 1; off < 32; off <<= 1) {
        unsigned int t = __shfl_up_sync(0xFFFFFFFFu, v, off);
        if (lane >= (unsigned)off) v += t;
    }
    if (lane == 31) wsum[wid] = v;
    __syncthreads();

    unsigned int w  = (lane < 16u) ? wsum[lane] : 0u;
    unsigned int wi = w;
    #pragma unroll
    for (int off = 1; off < 16; off <<= 1) {
        unsigned int t = __shfl_up_sync(0xFFFFFFFFu, wi, off);
        if (lane >= (unsigned)off) wi += t;
    }
    const unsigned int warp_base = __shfl_sync(0xFFFFFFFFu, wi - w, wid);
    const unsigned int base = warp_base + (v - csum);

    if (rank - base < csum) {   // unsigned in-range trick
        unsigned int r = rank - base;
        unsigned int d = (unsigned int)tid * 4u;
        if (r >= a.x) { r -= a.x; d++;
            if (r >= a.y) { r -= a.y; d++;
                if (r >= a.z) { r -= a.z; d++; } } }
        s_pr[0] = d;
        s_pr[1] = r;
    }
    __syncthreads();
}

__global__ __launch_bounds__(NTHREADS, 4)
void MaxoutDynamic_kernel(const float* __restrict__ feat, float* __restrict__ out) {
    __shared__ __align__(16) unsigned int hist[NBINS];     // 8 KB
    __shared__ __align__(16) unsigned int cand[CAND_MAX];  // 2 KB
    __shared__ unsigned int wsum[16];
    __shared__ unsigned int s_pr[2];   // {bin, rank-in-bin}
    __shared__ unsigned int s_key, s_cnt;

    const int tid = threadIdx.x;
    const unsigned int lane = tid & 31;
    const unsigned int wid  = tid >> 5;
    const size_t row_off = (size_t)blockIdx.x * FEAT;

    // ---- load row (2 x float4), zero histogram while loads are in flight ----
    const float4* in4 = reinterpret_cast<const float4*>(feat + row_off);
    float4 va = in4[tid];
    float4 vb = in4[tid + NTHREADS];

    uint4* h4 = reinterpret_cast<uint4*>(hist);
    const uint4 z4 = make_uint4(0u, 0u, 0u, 0u);
    h4[tid] = z4;
    if (tid == 0) { s_cnt = 0u; s_pr[0] = 0xFFFFFFFFu; }

    unsigned int key[PER];
    key[0] = fkey(va.x); key[1] = fkey(va.y); key[2] = fkey(va.z); key[3] = fkey(va.w);
    key[4] = fkey(vb.x); key[5] = fkey(vb.y); key[6] = fkey(vb.z); key[7] = fkey(vb.w);

    // ---- count keys below the interval (no atomics) ----
    unsigned int cl = 0;
    #pragma unroll
    for (int e = 0; e < PER; e++) cl += (key[e] < K_LO);
    #pragma unroll
    for (int off = 16; off; off >>= 1) cl += __shfl_xor_sync(0xFFFFFFFFu, cl, off);
    if (lane == 0) wsum[wid] = cl;
    __syncthreads();   // orders hist zeroing + wsum before use

    unsigned int tl = (lane < 16u) ? wsum[lane] : 0u;
    #pragma unroll
    for (int off = 16; off; off >>= 1) tl += __shfl_xor_sync(0xFFFFFFFFu, tl, off);
    const unsigned int rank0 = SEL_RANK - tl;   // rank among interval candidates (may wrap)

    // ---- histogram ONLY interval candidates (~400/row) ----
    #pragma unroll
    for (int e = 0; e < PER; e++) {
        unsigned int k = key[e];
        if (k - K_LO < (K_HI - K_LO))   // k in [K_LO, K_HI)
            atomicAdd(&hist[(k >> 20) - BIN_BASE], 1u);
    }
    __syncthreads();

    scan_select(hist, wsum, s_pr, rank0, tid, lane, wid);

    unsigned int sel = s_pr[0];
    unsigned int m_shift = 20, m_base = BIN_BASE;

    // ---- fallback (block-uniform, ~never taken): full histogram over k>>21 ----
    if (sel == 0xFFFFFFFFu) {
        h4[tid] = z4;
        __syncthreads();
        #pragma unroll
        for (int e = 0; e < PER; e++)
            atomicAdd(&hist[key[e] >> 21], 1u);
        __syncthreads();
        scan_select(hist, wsum, s_pr, SEL_RANK, tid, lane, wid);
        sel = s_pr[0];
        m_shift = 21; m_base = 0;
    }
    const unsigned int rb = s_pr[1];

    // ---- append candidates in the selected bin (typically ~3-30 total) ----
    #pragma unroll
    for (int e = 0; e < PER; e++) {
        if (((key[e] >> m_shift) - m_base) == sel) {
            unsigned int idx = atomicAdd(&s_cnt, 1u);
            if (idx < CAND_MAX) cand[idx] = key[e];
        }
    }
    __syncthreads();

    // ---- warp 0: exact rank-rb selection among n candidates (stable) ----
    if (wid == 0) {
        unsigned int n = s_cnt;
        if (n > CAND_MAX) n = CAND_MAX;
        for (unsigned int i = lane; i < n; i += 32) {
            unsigned int k = cand[i];
            unsigned int cnt = 0;
            for (unsigned int j = 0; j < n; j++) {
                unsigned int kj = cand[j];
                cnt += (kj < k) || (kj == k && j < i);
            }
            if (cnt == rb) s_key = k;   // exactly one winner
        }
    }
    __syncthreads();

    const unsigned int K = s_key;   // exact 32-bit threshold key

    // ---- predicated scaled writeback ----
    float4* out4 = reinterpret_cast<float4*>(out + row_off);
    float4 r0, r1;
    r0.x = (key[0] >= K) ? SCALE * kinv(key[0]) : 0.0f;
    r0.y = (key[1] >= K) ? SCALE * kinv(key[1]) : 0.0f;
    r0.z = (key[2] >= K) ? SCALE * kinv(key[2]) : 0.0f;
    r0.w = (key[3] >= K) ? SCALE * kinv(key[3]) : 0.0f;
    r1.x = (key[4] >= K) ? SCALE * kinv(key[4]) : 0.0f;
    r1.y = (key[5] >= K) ? SCALE * kinv(key[5]) : 0.0f;
    r1.z = (key[6] >= K) ? SCALE * kinv(key[6]) : 0.0f;
    r1.w = (key[7] >= K) ? SCALE * kinv(key[7]) : 0.0f;
    out4[tid]            = r0;
    out4[tid + NTHREADS] = r1;
}

extern "C" void kernel_launch(void* const* d_in, const int* in_sizes, int n_in,
                              void* d_out, int out_size) {
    const float* feat = (const float*)d_in[0];
    float* out = (float*)d_out;
    const int rows = in_sizes[0] / FEAT;   // 16384
    MaxoutDynamic_kernel<<<rows, NTHREADS>>>(feat, out);
}

// round 7
// speedup vs baseline: 1.0439x; 1.0439x over previous
#include <cuda_runtime.h>
#include <cuda_bf16.h>

#define FEAT      4096
#define NTHREADS  512
#define PER       8           // FEAT / NTHREADS
#define SEL_RANK  2048u       // 0-indexed rank of smallest KEPT element
#define NBINS     2048
#define CAND_MAX  512
#define F_LO      (-0.125f)
#define F_HI      (0.125f)
#define BIN_BASE  0x41Fu      // fkey(-0.125f) >> 20

// monotone fp32 -> u32 key (ascending float order == ascending uint order)
__device__ __forceinline__ unsigned int fkey(float f) {
    unsigned int u = __float_as_uint(f);
    return u ^ ((unsigned int)((int)u >> 31) | 0x80000000u);
}
// inverse key -> fp32 (branchless)
__device__ __forceinline__ float kinv(unsigned int k) {
    unsigned int m = (unsigned int)((int)(~k) >> 31) | 0x80000000u;
    return __uint_as_float(k ^ m);
}

// Scan a 2048-bin shared histogram (4 bins/thread), select the bin containing
// `rank`. Writes s_pr[0]=bin, s_pr[1]=rank-within-bin; writes nothing if rank
// is out of range (incl. unsigned wrap). Contains 2 __syncthreads().
__device__ __forceinline__ void scan_select(unsigned int* hist, unsigned int* wsum,
                                            unsigned int* s_pr, unsigned int rank,
                                            int tid, unsigned int lane, unsigned int wid)
{
    uint4 a = reinterpret_cast<uint4*>(hist)[tid];
    const unsigned int csum = a.x + a.y + a.z + a.w;
    unsigned int v = csum;
    #pragma unroll
    for (int off = 1; off < 32; off <<= 1) {
        unsigned int t = __shfl_up_sync(0xFFFFFFFFu, v, off);
        if (lane >= (unsigned)off) v += t;
    }
    if (lane == 31) wsum[wid] = v;
    __syncthreads();

    unsigned int w  = (lane < 16u) ? wsum[lane] : 0u;
    unsigned int wi = w;
    #pragma unroll
    for (int off = 1; off < 16; off <<= 1) {
        unsigned int t = __shfl_up_sync(0xFFFFFFFFu, wi, off);
        if (lane >= (unsigned)off) wi += t;
    }
    const unsigned int warp_base = __shfl_sync(0xFFFFFFFFu, wi - w, wid);
    const unsigned int base = warp_base + (v - csum);

    if (rank - base < csum) {   // unsigned in-range trick
        unsigned int r = rank - base;
        unsigned int d = (unsigned int)tid * 4u;
        if (r >= a.x) { r -= a.x; d++;
            if (r >= a.y) { r -= a.y; d++;
                if (r >= a.z) { r -= a.z; d++; } } }
        s_pr[0] = d;
        s_pr[1] = r;
    }
    __syncthreads();
}

__global__ __launch_bounds__(NTHREADS, 4)
void MaxoutDynamic_kernel(const float* __restrict__ feat, float* __restrict__ out) {
    __shared__ __align__(16) unsigned int hist[NBINS];     // 8 KB
    __shared__ __align__(16) unsigned int cand[CAND_MAX];  // 2 KB
    __shared__ unsigned int wsum[16];
    __shared__ unsigned int s_pr[2];   // {bin, rank-in-bin}
    __shared__ unsigned int s_key, s_cnt;

    const int tid = threadIdx.x;
    const unsigned int lane = tid & 31;
    const unsigned int wid  = tid >> 5;
    const size_t row_off = (size_t)blockIdx.x * FEAT;

    // ---- load row (2 x float4), zero histogram while loads are in flight ----
    const float4* in4 = reinterpret_cast<const float4*>(feat + row_off);
    float4 va = in4[tid];
    float4 vb = in4[tid + NTHREADS];

    uint4* h4 = reinterpret_cast<uint4*>(hist);
    const uint4 z4 = make_uint4(0u, 0u, 0u, 0u);
    h4[tid] = z4;
    if (tid == 0) { s_cnt = 0u; s_pr[0] = 0xFFFFFFFFu; }

    float f[PER];
    f[0] = va.x; f[1] = va.y; f[2] = va.z; f[3] = va.w;
    f[4] = vb.x; f[5] = vb.y; f[6] = vb.z; f[7] = vb.w;

    // ---- count elements strictly below the interval (pure float compares) ----
    unsigned int cb = 0;
    #pragma unroll
    for (int e = 0; e < PER; e++) cb += (f[e] < F_LO);
    cb = __reduce_add_sync(0xFFFFFFFFu, cb);
    if (lane == 0) wsum[wid] = cb;
    __syncthreads();   // also orders hist zeroing before atomics

    const unsigned int tl = __reduce_add_sync(0xFFFFFFFFu, (lane < 16u) ? wsum[lane] : 0u);
    const unsigned int rank0 = SEL_RANK - tl;   // rank among interval candidates (may wrap)

    // ---- histogram ONLY interval candidates (~400/row), lazy key compute ----
    #pragma unroll
    for (int e = 0; e < PER; e++) {
        if (fabsf(f[e]) <= F_HI)
            atomicAdd(&hist[(fkey(f[e]) >> 20) - BIN_BASE], 1u);
    }
    __syncthreads();

    scan_select(hist, wsum, s_pr, rank0, tid, lane, wid);

    unsigned int sel = s_pr[0];
    unsigned int rb;
    if (sel != 0xFFFFFFFFu) {
        rb = s_pr[1];
        // append candidates in the selected bin (typically ~3-30 total)
        #pragma unroll
        for (int e = 0; e < PER; e++) {
            if (fabsf(f[e]) <= F_HI) {
                unsigned int k = fkey(f[e]);
                if (((k >> 20) - BIN_BASE) == sel) {
                    unsigned int idx = atomicAdd(&s_cnt, 1u);
                    if (idx < CAND_MAX) cand[idx] = k;
                }
            }
        }
    } else {
        // ---- fallback (block-uniform, ~never taken): full hist over k>>21 ----
        h4[tid] = z4;
        __syncthreads();
        #pragma unroll
        for (int e = 0; e < PER; e++)
            atomicAdd(&hist[fkey(f[e]) >> 21], 1u);
        __syncthreads();
        scan_select(hist, wsum, s_pr, SEL_RANK, tid, lane, wid);
        sel = s_pr[0];
        rb  = s_pr[1];
        #pragma unroll
        for (int e = 0; e < PER; e++) {
            unsigned int k = fkey(f[e]);
            if ((k >> 21) == sel) {
                unsigned int idx = atomicAdd(&s_cnt, 1u);
                if (idx < CAND_MAX) cand[idx] = k;
            }
        }
    }
    __syncthreads();

    // ---- warp 0: exact rank-rb selection among n candidates (stable) ----
    if (wid == 0) {
        unsigned int n = s_cnt;
        if (n > CAND_MAX) n = CAND_MAX;
        for (unsigned int i = lane; i < n; i += 32) {
            unsigned int k = cand[i];
            unsigned int cnt = 0;
            for (unsigned int j = 0; j < n; j++) {
                unsigned int kj = cand[j];
                cnt += (kj < k) || (kj == k && j < i);
            }
            if (cnt == rb) s_key = k;   // exactly one winner
        }
    }
    __syncthreads();

    // exact float threshold; key >= K  <=>  f >= T (monotone map)
    const float T = kinv(s_key);

    // ---- predicated scaled writeback, pure float ops ----
    float4* out4 = reinterpret_cast<float4*>(out + row_off);
    float4 r0, r1;
    r0.x = (f[0] >= T) ? 2.0f * f[0] : 0.0f;
    r0.y = (f[1] >= T) ? 2.0f * f[1] : 0.0f;
    r0.z = (f[2] >= T) ? 2.0f * f[2] : 0.0f;
    r0.w = (f[3] >= T) ? 2.0f * f[3] : 0.0f;
    r1.x = (f[4] >= T) ? 2.0f * f[4] : 0.0f;
    r1.y = (f[5] >= T) ? 2.0f * f[5] : 0.0f;
    r1.z = (f[6] >= T) ? 2.0f * f[6] : 0.0f;
    r1.w = (f[7] >= T) ? 2.0f * f[7] : 0.0f;
    out4[tid]            = r0;
    out4[tid + NTHREADS] = r1;
}

extern "C" void kernel_launch(void* const* d_in, const int* in_sizes, int n_in,
                              void* d_out, int out_size) {
    const float* feat = (const float*)d_in[0];
    float* out = (float*)d_out;
    const int rows = in_sizes[0] / FEAT;   // 16384
    MaxoutDynamic_kernel<<<rows, NTHREADS>>>(feat, out);
}

// round 8
// speedup vs baseline: 1.0457x; 1.0017x over previous
#include <cuda_runtime.h>
#include <cuda_bf16.h>

#define FEAT      4096
#define NTHREADS  512
#define PER       8           // FEAT / NTHREADS
#define SEL_RANK  2048u       // 0-indexed rank of smallest KEPT element
#define SLOT_CAP  16

// monotone fp32 -> u32 key (fallback path only)
__device__ __forceinline__ unsigned int fkey(float f) {
    unsigned int u = __float_as_uint(f);
    return u ^ ((unsigned int)((int)u >> 31) | 0x80000000u);
}
__device__ __forceinline__ float kinv(unsigned int k) {
    unsigned int m = (unsigned int)((int)(~k) >> 31) | 0x80000000u;
    return __uint_as_float(k ^ m);
}

// Warp-0-only: scan a 256-bin shared histogram (8 bins/lane), find the bin
// containing `rank`. Writes *s_sel (bin) and *s_rank (rank within bin); if
// rank is out of range (incl. unsigned wrap) nothing is written.
__device__ __forceinline__ void warp_select256(const unsigned int* hist, unsigned int rank,
                                               unsigned int* s_sel, unsigned int* s_rank)
{
    const unsigned int lane = threadIdx.x & 31;
    uint4 a = reinterpret_cast<const uint4*>(hist)[2 * lane];
    uint4 b = reinterpret_cast<const uint4*>(hist)[2 * lane + 1];
    unsigned int c[8] = {a.x, a.y, a.z, a.w, b.x, b.y, b.z, b.w};
    unsigned int csum = c[0]+c[1]+c[2]+c[3]+c[4]+c[5]+c[6]+c[7];
    unsigned int v = csum;
    #pragma unroll
    for (int off = 1; off < 32; off <<= 1) {
        unsigned int t = __shfl_up_sync(0xFFFFFFFFu, v, off);
        if (lane >= (unsigned)off) v += t;
    }
    const unsigned int base = v - csum;
    if (rank - base < csum) {            // unsigned in-range trick
        unsigned int r = rank - base;
        unsigned int d = lane * 8u;
        #pragma unroll
        for (int i = 0; i < 7; i++) {
            if (r >= c[i]) { r -= c[i]; d++; }
            else break;
        }
        *s_sel  = d;
        *s_rank = r;
    }
}

__global__ __launch_bounds__(NTHREADS, 4)
void MaxoutDynamic_kernel(const float* __restrict__ feat, float* __restrict__ out) {
    __shared__ __align__(16) unsigned int hist[256];          // 1 KB
    __shared__ __align__(16) float slots[256 * SLOT_CAP];     // 16 KB
    __shared__ unsigned int wsum[16];
    __shared__ unsigned int s_sel, s_rank, s_state;
    __shared__ float s_T;

    const int tid = threadIdx.x;
    const unsigned int lane = tid & 31;
    const unsigned int wid  = tid >> 5;
    const size_t row_off = (size_t)blockIdx.x * FEAT;

    // ---- load row (2 x float4) ----
    const float4* in4 = reinterpret_cast<const float4*>(feat + row_off);
    float4 va = in4[tid];
    float4 vb = in4[tid + NTHREADS];

    if (tid < 64) reinterpret_cast<uint4*>(hist)[tid] = make_uint4(0u,0u,0u,0u);
    if (tid == 0) { s_sel = 0xFFFFFFFFu; s_state = 0u; }
    __syncthreads();   // B1: hist zeroed before atomics

    float f[PER] = {va.x, va.y, va.z, va.w, vb.x, vb.y, vb.z, vb.w};

    // ---- ONE pass: bin, below-count, counting-sort into slots ----
    // bin(f) = floor(f*1024 + 128): monotone; bin<0 <=> f below interval,
    // bin in [0,256) <=> f in [-0.125, 0.125) (threshold ~ N(0, 0.02) -> 6+ sigma margin)
    unsigned int below = 0;
    #pragma unroll
    for (int e = 0; e < PER; e++) {
        int bin = __float2int_rd(fmaf(f[e], 1024.0f, 128.0f));
        below += ((unsigned int)bin) >> 31;
        if ((unsigned int)bin < 256u) {
            unsigned int old = atomicAdd(&hist[bin], 1u);
            if (old < SLOT_CAP) slots[bin * SLOT_CAP + old] = f[e];
        }
    }
    below = __reduce_add_sync(0xFFFFFFFFu, below);
    if (lane == 0) wsum[wid] = below;
    __syncthreads();   // B2

    // ---- warp 0: select bin, rank slot floats exactly ----
    if (wid == 0) {
        const unsigned int tot_below =
            __reduce_add_sync(0xFFFFFFFFu, (lane < 16u) ? wsum[lane] : 0u);
        const unsigned int rank0 = SEL_RANK - tot_below;   // may wrap -> fallback
        warp_select256(hist, rank0, &s_sel, &s_rank);
        __syncwarp();
        const unsigned int sel = s_sel;
        if (sel == 0xFFFFFFFFu) {
            if (lane == 0) s_state = 1u;
        } else {
            const unsigned int cnt = hist[sel];
            if (cnt > SLOT_CAP) {
                if (lane == 0) s_state = 1u;   // selected-bin overflow (~never)
            } else {
                const unsigned int rb = s_rank;
                float fi = (lane < cnt) ? slots[sel * SLOT_CAP + lane] : 0.0f;
                unsigned int cl = 0;
                for (unsigned int j = 0; j < cnt; j++) {
                    float fj = __shfl_sync(0xFFFFFFFFu, fi, j);
                    cl += (fj < fi) || (fj == fi && j < lane);
                }
                if (lane < cnt && cl == rb) s_T = fi;   // exactly one winner
            }
        }
    }
    __syncthreads();   // B3

    float T;
    if (s_state == 0u) {
        T = s_T;
    } else {
        // ---- general exact fallback (block-uniform, ~never taken):
        //      4-pass 8-bit MSB radix select over monotone keys ----
        unsigned int key[PER];
        #pragma unroll
        for (int e = 0; e < PER; e++) key[e] = fkey(f[e]);
        unsigned int prefix = 0u, pmask = 0u, rnk = SEL_RANK;
        for (int p = 0; p < 4; p++) {
            const int shift = 24 - 8 * p;
            __syncthreads();
            if (tid < 64) reinterpret_cast<uint4*>(hist)[tid] = make_uint4(0u,0u,0u,0u);
            if (tid == 0) s_sel = 0xFFFFFFFFu;
            __syncthreads();
            #pragma unroll
            for (int e = 0; e < PER; e++)
                if ((key[e] & pmask) == prefix)
                    atomicAdd(&hist[(key[e] >> shift) & 255u], 1u);
            __syncthreads();
            if (wid == 0) warp_select256(hist, rnk, &s_sel, &s_rank);
            __syncthreads();
            prefix |= s_sel << shift;
            pmask  |= 255u << shift;
            rnk = s_rank;
        }
        T = kinv(prefix);
    }

    // ---- predicated scaled writeback ----
    float4* out4 = reinterpret_cast<float4*>(out + row_off);
    float4 r0, r1;
    r0.x = (f[0] >= T) ? 2.0f * f[0] : 0.0f;
    r0.y = (f[1] >= T) ? 2.0f * f[1] : 0.0f;
    r0.z = (f[2] >= T) ? 2.0f * f[2] : 0.0f;
    r0.w = (f[3] >= T) ? 2.0f * f[3] : 0.0f;
    r1.x = (f[4] >= T) ? 2.0f * f[4] : 0.0f;
    r1.y = (f[5] >= T) ? 2.0f * f[5] : 0.0f;
    r1.z = (f[6] >= T) ? 2.0f * f[6] : 0.0f;
    r1.w = (f[7] >= T) ? 2.0f * f[7] : 0.0f;
    out4[tid]            = r0;
    out4[tid + NTHREADS] = r1;
}

extern "C" void kernel_launch(void* const* d_in, const int* in_sizes, int n_in,
                              void* d_out, int out_size) {
    const float* feat = (const float*)d_in[0];
    float* out = (float*)d_out;
    const int rows = in_sizes[0] / FEAT;   // 16384
    MaxoutDynamic_kernel<<<rows, NTHREADS>>>(feat, out);
}